// round 9
// baseline (speedup 1.0000x reference)
#include <cuda_runtime.h>
#include <cuda_fp16.h>
#include <math.h>
#include <string.h>

#define H_    512
#define W_    1408
#define HW    (H_ * W_)        // 720896 = 704 * 1024
#define NPTS  640000
#define NCAM  6
#define NCH   17

// Scratch (allocation-free rule: __device__ globals).
// Ping-pong buffers. Main image: 16 channels/pixel fp16 = 32B/pixel (23MB).
// Channel 16 lives in a separate planar half array (1.4MB).
// Invariant: zero at entry of every kernel_launch; loss(c) re-zeroes the
// buffer it reads; next user of that buffer is 2 kernels downstream.
__device__ __align__(256) __half g16[2][(size_t)HW * 16];
__device__ __align__(256) __half g1[2][(size_t)HW + 16];  // +16 pad for merged window writes
__device__ float g_num[NCAM];
__device__ float g_den[NCAM];

__device__ __forceinline__ unsigned h2_bits(__half2 h) {
    unsigned u;
    memcpy(&u, &h, 4);
    return u;
}

__device__ __forceinline__ void red_add_v4_h2(__half* addr, unsigned a, unsigned b,
                                              unsigned c, unsigned d) {
    asm volatile("red.global.add.noftz.v4.f16x2 [%0], {%1, %2, %3, %4};"
                 :: "l"(addr), "r"(a), "r"(b), "r"(c), "r"(d)
                 : "memory");
}
__device__ __forceinline__ void red_add_h2(__half* addr, __half2 v) {
    asm volatile("red.global.add.noftz.f16x2 [%0], %1;"
                 :: "l"(addr), "r"(h2_bits(v))
                 : "memory");
}
__device__ __forceinline__ void red_add_h(__half* addr, __half v) {
    unsigned short s;
    memcpy(&s, &v, 2);
    asm volatile("red.global.add.noftz.f16 [%0], %1;"
                 :: "l"(addr), "h"(s)
                 : "memory");
}

__global__ __launch_bounds__(256)
void splat_kernel(int cam, int buf,
                  const float* __restrict__ feats,
                  const float* __restrict__ density,
                  const float* __restrict__ viewmats,
                  const float* __restrict__ Ks,
                  const float* __restrict__ xyz)
{
    int p = blockIdx.x * 256 + threadIdx.x;
    if (p >= NPTS) return;

    float X = __ldcs(xyz + 3 * p + 0);
    float Y = __ldcs(xyz + 3 * p + 1);
    float Z = __ldcs(xyz + 3 * p + 2);

    const float* V = viewmats + cam * 16;
    const float* K = Ks + cam * 9;

    float px = V[0] * X + V[1] * Y + V[2]  * Z + V[3];
    float py = V[4] * X + V[5] * Y + V[6]  * Z + V[7];
    float pz = V[8] * X + V[9] * Y + V[10] * Z + V[11];

    // reference: valid requires p.z > 0.1 (else all 9 taps contribute 0)
    if (!(pz > 0.1f)) return;

    float z  = fmaxf(pz, 0.001f);
    float fx = K[0], cx = K[2], fy = K[4], cy = K[5];

    float u = fx * px / z + cx;
    float v = fy * py / z + cy;

    const float s2 = 0.4f * 0.4f;
    float j00 = fx / z;
    float j11 = fy / z;
    float j02 = -fx * px / (z * z);
    float j12 = -fy * py / (z * z);

    float a = s2 * (j00 * j00 + j02 * j02) + 0.3f;
    float b = s2 * (j02 * j12);
    float c = s2 * (j11 * j11 + j12 * j12) + 0.3f;
    float det = a * c - b * b;
    float ca =  c / det;
    float cb = -b / det;
    float cc =  a / det;

    float ru = rintf(u);   // matches jnp.round (half-to-even)
    float rv = rintf(v);

    // quick full-footprint reject (all 9 taps out of image)
    if (ru < -1.0f || ru > (float)W_ || rv < -1.0f || rv > (float)H_) return;

    float opac = __ldcs(density + p);

    // Pack the 17-ch feature vector into half2 registers (pad with 0).
    __half2 fh[8];
    __half  f16h;
    {
        float f[NCH];
#pragma unroll
        for (int ch = 0; ch < NCH; ch++) f[ch] = __ldcs(feats + (size_t)p * NCH + ch);
#pragma unroll
        for (int i = 0; i < 8; i++) fh[i] = __floats2half2_rn(f[2 * i], f[2 * i + 1]);
        f16h = __float2half_rn(f[16]);
    }

    __half* img16 = g16[buf];
    __half* img1  = g1[buf];

    int   iu      = (int)ru;
    bool  u_inner = (ru >= 1.0f) && (ru <= (float)(W_ - 2));  // all 3 dx taps in-bounds

#pragma unroll
    for (int r = 0; r < 3; r++) {
        float pyy = rv + (float)(r - 1);
        if (pyy < 0.0f || pyy >= (float)H_) continue;
        float ddy = pyy - v;
        int   rowbase = (int)pyy * W_ + iu - 1;   // pixel index of dx=-1 tap

        if (u_inner) {
            __half c16[3];
#pragma unroll
            for (int t = 0; t < 3; t++) {
                float ddx = (ru + (float)(t - 1)) - u;
                float e = -0.5f * (ca * ddx * ddx + 2.0f * cb * ddx * ddy + cc * ddy * ddy);
                float w = opac * __expf(e);
                __half2 wh = __float2half2_rn(w);

                __half* bp = img16 + (size_t)(rowbase + t) * 16;
                red_add_v4_h2(bp + 0, h2_bits(__hmul2(wh, fh[0])), h2_bits(__hmul2(wh, fh[1])),
                                      h2_bits(__hmul2(wh, fh[2])), h2_bits(__hmul2(wh, fh[3])));
                red_add_v4_h2(bp + 8, h2_bits(__hmul2(wh, fh[4])), h2_bits(__hmul2(wh, fh[5])),
                                      h2_bits(__hmul2(wh, fh[6])), h2_bits(__hmul2(wh, fh[7])));
                c16[t] = __hmul(__low2half(wh), f16h);
            }
            // merged ch16: place 3 halves inside one 16B-aligned 8-half window
            // when they fit (off<=5, 75% of rows): ONE v4.f16x2 RED with +0 pads.
            int e2  = rowbase & ~7;          // 8-half (16B) aligned base
            int off = rowbase - e2;          // 0..7
            unsigned short s0, s1, s2w;
            memcpy(&s0, &c16[0], 2); memcpy(&s1, &c16[1], 2); memcpy(&s2w, &c16[2], 2);
            if (off <= 5) {
                unsigned long long vv = (unsigned long long)s0
                                      | ((unsigned long long)s1 << 16)
                                      | ((unsigned long long)s2w << 32);
                int sh = off * 16;           // 0..80
                unsigned long long lo, hi;
                if (sh == 0)       { lo = vv;              hi = 0ull; }
                else if (sh < 64)  { lo = vv << sh;        hi = vv >> (64 - sh); }
                else               { lo = 0ull;            hi = vv << (sh - 64); }
                red_add_v4_h2(img1 + e2,
                              (unsigned)lo, (unsigned)(lo >> 32),
                              (unsigned)hi, (unsigned)(hi >> 32));
            } else if (off == 6) {           // rowbase even: pair at rowbase, scalar at +2
                red_add_h2(img1 + rowbase, __halves2half2(c16[0], c16[1]));
                red_add_h(img1 + rowbase + 2, c16[2]);
            } else {                          // off == 7, rowbase odd
                red_add_h(img1 + rowbase, c16[0]);
                red_add_h2(img1 + rowbase + 1, __halves2half2(c16[1], c16[2]));
            }
        } else {
            // border fallback: per-tap guarded (matches reference exactly)
#pragma unroll
            for (int t = 0; t < 3; t++) {
                float pxx = ru + (float)(t - 1);
                if (pxx < 0.0f || pxx >= (float)W_) continue;
                float ddx = pxx - u;
                float e = -0.5f * (ca * ddx * ddx + 2.0f * cb * ddx * ddy + cc * ddy * ddy);
                float w = opac * __expf(e);
                __half2 wh = __float2half2_rn(w);
                int pix = rowbase + t;
                __half* bp = img16 + (size_t)pix * 16;
                red_add_v4_h2(bp + 0, h2_bits(__hmul2(wh, fh[0])), h2_bits(__hmul2(wh, fh[1])),
                                      h2_bits(__hmul2(wh, fh[2])), h2_bits(__hmul2(wh, fh[3])));
                red_add_v4_h2(bp + 8, h2_bits(__hmul2(wh, fh[4])), h2_bits(__hmul2(wh, fh[5])),
                                      h2_bits(__hmul2(wh, fh[6])), h2_bits(__hmul2(wh, fh[7])));
                red_add_h(img1 + pix, __hmul(__low2half(wh), f16h));
            }
        }
    }
}

// Loss: 352 blocks x 256 threads x 8 pixels (MLP-heavy).
// Triggers PDL completion at entry so the next splat (other buffer) overlaps.
__global__ __launch_bounds__(256)
void loss_kernel(int cam, int buf, const int* __restrict__ gt, const float* __restrict__ cw)
{
#if __CUDA_ARCH__ >= 900
    cudaTriggerProgrammaticLaunchCompletion();
#endif

    float nwl = 0.0f, wv = 0.0f;
    __half* img16 = g16[buf];
    __half* img1  = g1[buf];

#pragma unroll
    for (int j = 0; j < 8; j++) {
        int pix = blockIdx.x * 2048 + j * 256 + threadIdx.x;
        __half* bp = img16 + (size_t)pix * 16;

        uint4 q0 = ((const uint4*)bp)[0];   // halves 0..7
        uint4 q1 = ((const uint4*)bp)[1];   // halves 8..15
        __half h16 = img1[pix];

        float l[NCH];
        {
            float2 t;
            t = __half22float2(*(__half2*)&q0.x); l[0] = t.x;  l[1] = t.y;
            t = __half22float2(*(__half2*)&q0.y); l[2] = t.x;  l[3] = t.y;
            t = __half22float2(*(__half2*)&q0.z); l[4] = t.x;  l[5] = t.y;
            t = __half22float2(*(__half2*)&q0.w); l[6] = t.x;  l[7] = t.y;
            t = __half22float2(*(__half2*)&q1.x); l[8] = t.x;  l[9] = t.y;
            t = __half22float2(*(__half2*)&q1.y); l[10] = t.x; l[11] = t.y;
            t = __half22float2(*(__half2*)&q1.z); l[12] = t.x; l[13] = t.y;
            t = __half22float2(*(__half2*)&q1.w); l[14] = t.x; l[15] = t.y;
            l[16] = __half2float(h16);
        }

        float m = l[0];
#pragma unroll
        for (int ch = 1; ch < NCH; ch++) m = fmaxf(m, l[ch]);
        float s = 0.0f;
#pragma unroll
        for (int ch = 0; ch < NCH; ch++) s += __expf(l[ch] - m);
        float lse = m + __logf(s);

        int g = __ldcs(gt + (size_t)cam * HW + pix);  // in [0,17)
        float lg = (g < 16) ? __half2float(bp[g]) : l[16];
        float w = (g != 0) ? cw[g] : 0.0f;

        nwl += w * (lse - lg);
        wv  += w;

        // restore invariant: zero the image before this buffer's next splat
        uint4 z4 = make_uint4(0u, 0u, 0u, 0u);
        ((uint4*)bp)[0] = z4;
        ((uint4*)bp)[1] = z4;
        img1[pix] = __ushort_as_half((unsigned short)0);
    }

    // block reduction
#pragma unroll
    for (int o = 16; o > 0; o >>= 1) {
        nwl += __shfl_down_sync(0xffffffffu, nwl, o);
        wv  += __shfl_down_sync(0xffffffffu, wv,  o);
    }
    __shared__ float sh[16];
    int lane = threadIdx.x & 31;
    int wid  = threadIdx.x >> 5;
    if (lane == 0) { sh[wid] = nwl; sh[8 + wid] = wv; }
    __syncthreads();
    if (threadIdx.x == 0) {
        float an = 0.0f, ad = 0.0f;
#pragma unroll
        for (int i = 0; i < 8; i++) { an += sh[i]; ad += sh[8 + i]; }
        atomicAdd(&g_num[cam], an);
        atomicAdd(&g_den[cam], ad);
    }
}

__global__ void finalize_kernel(float* out)
{
    if (threadIdx.x == 0 && blockIdx.x == 0) {
        float L = 0.0f;
#pragma unroll
        for (int cam = 0; cam < NCAM; cam++) {
            L += g_num[cam] / fmaxf(g_den[cam], 1e-8f);
            g_num[cam] = 0.0f;   // reset accumulators for next replay
            g_den[cam] = 0.0f;
        }
        out[0] = L / (float)NCAM;
    }
}

extern "C" void kernel_launch(void* const* d_in, const int* in_sizes, int n_in,
                              void* d_out, int out_size)
{
    const float* voxel_feats = (const float*)d_in[0];
    const float* density     = (const float*)d_in[1];
    const float* viewmats    = (const float*)d_in[2];
    const float* Ks          = (const float*)d_in[3];
    const int*   gt_sem      = (const int*)d_in[4];
    const float* pc_xyz      = (const float*)d_in[5];
    const float* cls_w       = (const float*)d_in[6];

    for (int cam = 0; cam < NCAM; cam++) {
        int buf = cam & 1;

        // splat with PDL: may start while the previous loss (other buffer) runs
        cudaLaunchConfig_t cfg = {};
        cfg.gridDim  = dim3((NPTS + 255) / 256);
        cfg.blockDim = dim3(256);
        cfg.stream   = 0;
        cudaLaunchAttribute attr;
        attr.id = cudaLaunchAttributeProgrammaticStreamSerialization;
        attr.val.programmaticStreamSerializationAllowed = 1;
        cfg.attrs = &attr;
        cfg.numAttrs = 1;
        cudaLaunchKernelEx(&cfg, splat_kernel, cam, buf,
                           voxel_feats, density, viewmats, Ks, pc_xyz);

        loss_kernel<<<HW / 2048, 256>>>(cam, buf, gt_sem, cls_w);
    }
    finalize_kernel<<<1, 32>>>((float*)d_out);
}

// round 10
// speedup vs baseline: 1.1321x; 1.1321x over previous
#include <cuda_runtime.h>
#include <cuda_fp16.h>
#include <math.h>
#include <string.h>

#define H_    512
#define W_    1408
#define HW    (H_ * W_)        // 720896 = 704 * 1024
#define NPTS  640000
#define NCAM  6
#define NCH   17

// Scratch (allocation-free rule: __device__ globals).
// Ping-pong buffers. Main image: 16 channels/pixel fp16 = 32B/pixel (23MB).
// Channel 16 lives in a separate planar half array (1.4MB).
// buf0 is owned by the even-camera chain, buf1 by the odd-camera chain;
// within a chain, loss(c) zeroes the buffer before splat(c+2) reuses it
// (same-stream ordering). Both buffers zero at entry of every launch.
__device__ __align__(256) __half g16[2][(size_t)HW * 16];
__device__ __align__(256) __half g1[2][(size_t)HW + 8];
__device__ float g_num[NCAM];
__device__ float g_den[NCAM];

__device__ __forceinline__ unsigned h2_bits(__half2 h) {
    unsigned u;
    memcpy(&u, &h, 4);
    return u;
}

__device__ __forceinline__ void red_add_v4_h2(__half* addr, unsigned a, unsigned b,
                                              unsigned c, unsigned d) {
    asm volatile("red.global.add.noftz.v4.f16x2 [%0], {%1, %2, %3, %4};"
                 :: "l"(addr), "r"(a), "r"(b), "r"(c), "r"(d)
                 : "memory");
}
__device__ __forceinline__ void red_add_h2(__half* addr, __half2 v) {
    asm volatile("red.global.add.noftz.f16x2 [%0], %1;"
                 :: "l"(addr), "r"(h2_bits(v))
                 : "memory");
}
__device__ __forceinline__ void red_add_h(__half* addr, __half v) {
    unsigned short s;
    memcpy(&s, &v, 2);
    asm volatile("red.global.add.noftz.f16 [%0], %1;"
                 :: "l"(addr), "h"(s)
                 : "memory");
}

__global__ __launch_bounds__(256)
void splat_kernel(int cam, int buf,
                  const float* __restrict__ feats,
                  const float* __restrict__ density,
                  const float* __restrict__ viewmats,
                  const float* __restrict__ Ks,
                  const float* __restrict__ xyz)
{
    int p = blockIdx.x * 256 + threadIdx.x;
    if (p >= NPTS) return;

    float X = __ldcs(xyz + 3 * p + 0);
    float Y = __ldcs(xyz + 3 * p + 1);
    float Z = __ldcs(xyz + 3 * p + 2);

    const float* V = viewmats + cam * 16;
    const float* K = Ks + cam * 9;

    float px = V[0] * X + V[1] * Y + V[2]  * Z + V[3];
    float py = V[4] * X + V[5] * Y + V[6]  * Z + V[7];
    float pz = V[8] * X + V[9] * Y + V[10] * Z + V[11];

    // reference: valid requires p.z > 0.1 (else all 9 taps contribute 0)
    if (!(pz > 0.1f)) return;

    float z  = fmaxf(pz, 0.001f);
    float fx = K[0], cx = K[2], fy = K[4], cy = K[5];

    float u = fx * px / z + cx;
    float v = fy * py / z + cy;

    const float s2 = 0.4f * 0.4f;
    float j00 = fx / z;
    float j11 = fy / z;
    float j02 = -fx * px / (z * z);
    float j12 = -fy * py / (z * z);

    float a = s2 * (j00 * j00 + j02 * j02) + 0.3f;
    float b = s2 * (j02 * j12);
    float c = s2 * (j11 * j11 + j12 * j12) + 0.3f;
    float det = a * c - b * b;
    float ca =  c / det;
    float cb = -b / det;
    float cc =  a / det;

    float ru = rintf(u);   // matches jnp.round (half-to-even)
    float rv = rintf(v);

    // quick full-footprint reject (all 9 taps out of image)
    if (ru < -1.0f || ru > (float)W_ || rv < -1.0f || rv > (float)H_) return;

    float opac = __ldcs(density + p);

    // Pack the 17-ch feature vector into half2 registers (pad with 0).
    __half2 fh[8];
    __half  f16h;
    {
        float f[NCH];
#pragma unroll
        for (int ch = 0; ch < NCH; ch++) f[ch] = __ldcs(feats + (size_t)p * NCH + ch);
#pragma unroll
        for (int i = 0; i < 8; i++) fh[i] = __floats2half2_rn(f[2 * i], f[2 * i + 1]);
        f16h = __float2half_rn(f[16]);
    }

    __half* img16 = g16[buf];
    __half* img1  = g1[buf];

    int   iu      = (int)ru;
    bool  u_inner = (ru >= 1.0f) && (ru <= (float)(W_ - 2));  // all 3 dx taps in-bounds

#pragma unroll
    for (int r = 0; r < 3; r++) {
        float pyy = rv + (float)(r - 1);
        if (pyy < 0.0f || pyy >= (float)H_) continue;
        float ddy = pyy - v;
        int   rowbase = (int)pyy * W_ + iu - 1;   // pixel index of dx=-1 tap

        if (u_inner) {
            __half c16[3];
#pragma unroll
            for (int t = 0; t < 3; t++) {
                float ddx = (ru + (float)(t - 1)) - u;
                float e = -0.5f * (ca * ddx * ddx + 2.0f * cb * ddx * ddy + cc * ddy * ddy);
                float w = opac * __expf(e);
                __half2 wh = __float2half2_rn(w);

                __half* bp = img16 + (size_t)(rowbase + t) * 16;
                red_add_v4_h2(bp + 0, h2_bits(__hmul2(wh, fh[0])), h2_bits(__hmul2(wh, fh[1])),
                                      h2_bits(__hmul2(wh, fh[2])), h2_bits(__hmul2(wh, fh[3])));
                red_add_v4_h2(bp + 8, h2_bits(__hmul2(wh, fh[4])), h2_bits(__hmul2(wh, fh[5])),
                                      h2_bits(__hmul2(wh, fh[6])), h2_bits(__hmul2(wh, fh[7])));
                c16[t] = __hmul(__low2half(wh), f16h);
            }
            // merged ch16: 3 contiguous halves -> two 4B-aligned f16x2 REDs (+0 padding)
            const __half hz = __ushort_as_half((unsigned short)0);
            int  e2  = rowbase & ~1;
            bool odd = (rowbase & 1) != 0;
            __half2 h2a = odd ? __halves2half2(hz, c16[0]) : __halves2half2(c16[0], c16[1]);
            __half2 h2b = odd ? __halves2half2(c16[1], c16[2]) : __halves2half2(c16[2], hz);
            red_add_h2(img1 + e2,     h2a);
            red_add_h2(img1 + e2 + 2, h2b);
        } else {
            // border fallback: per-tap guarded (matches reference exactly)
#pragma unroll
            for (int t = 0; t < 3; t++) {
                float pxx = ru + (float)(t - 1);
                if (pxx < 0.0f || pxx >= (float)W_) continue;
                float ddx = pxx - u;
                float e = -0.5f * (ca * ddx * ddx + 2.0f * cb * ddx * ddy + cc * ddy * ddy);
                float w = opac * __expf(e);
                __half2 wh = __float2half2_rn(w);
                int pix = rowbase + t;
                __half* bp = img16 + (size_t)pix * 16;
                red_add_v4_h2(bp + 0, h2_bits(__hmul2(wh, fh[0])), h2_bits(__hmul2(wh, fh[1])),
                                      h2_bits(__hmul2(wh, fh[2])), h2_bits(__hmul2(wh, fh[3])));
                red_add_v4_h2(bp + 8, h2_bits(__hmul2(wh, fh[4])), h2_bits(__hmul2(wh, fh[5])),
                                      h2_bits(__hmul2(wh, fh[6])), h2_bits(__hmul2(wh, fh[7])));
                red_add_h(img1 + pix, __hmul(__low2half(wh), f16h));
            }
        }
    }
}

// Loss: 352 blocks x 256 threads x 8 pixels (MLP-heavy).
__global__ __launch_bounds__(256)
void loss_kernel(int cam, int buf, const int* __restrict__ gt, const float* __restrict__ cw)
{
    float nwl = 0.0f, wv = 0.0f;
    __half* img16 = g16[buf];
    __half* img1  = g1[buf];

#pragma unroll
    for (int j = 0; j < 8; j++) {
        int pix = blockIdx.x * 2048 + j * 256 + threadIdx.x;
        __half* bp = img16 + (size_t)pix * 16;

        uint4 q0 = ((const uint4*)bp)[0];   // halves 0..7
        uint4 q1 = ((const uint4*)bp)[1];   // halves 8..15
        __half h16 = img1[pix];

        float l[NCH];
        {
            float2 t;
            t = __half22float2(*(__half2*)&q0.x); l[0] = t.x;  l[1] = t.y;
            t = __half22float2(*(__half2*)&q0.y); l[2] = t.x;  l[3] = t.y;
            t = __half22float2(*(__half2*)&q0.z); l[4] = t.x;  l[5] = t.y;
            t = __half22float2(*(__half2*)&q0.w); l[6] = t.x;  l[7] = t.y;
            t = __half22float2(*(__half2*)&q1.x); l[8] = t.x;  l[9] = t.y;
            t = __half22float2(*(__half2*)&q1.y); l[10] = t.x; l[11] = t.y;
            t = __half22float2(*(__half2*)&q1.z); l[12] = t.x; l[13] = t.y;
            t = __half22float2(*(__half2*)&q1.w); l[14] = t.x; l[15] = t.y;
            l[16] = __half2float(h16);
        }

        float m = l[0];
#pragma unroll
        for (int ch = 1; ch < NCH; ch++) m = fmaxf(m, l[ch]);
        float s = 0.0f;
#pragma unroll
        for (int ch = 0; ch < NCH; ch++) s += __expf(l[ch] - m);
        float lse = m + __logf(s);

        int g = __ldcs(gt + (size_t)cam * HW + pix);  // in [0,17)
        float lg = (g < 16) ? __half2float(bp[g]) : l[16];
        float w = (g != 0) ? cw[g] : 0.0f;

        nwl += w * (lse - lg);
        wv  += w;

        // restore invariant: zero the image before this buffer's next splat
        uint4 z4 = make_uint4(0u, 0u, 0u, 0u);
        ((uint4*)bp)[0] = z4;
        ((uint4*)bp)[1] = z4;
        img1[pix] = __ushort_as_half((unsigned short)0);
    }

    // block reduction
#pragma unroll
    for (int o = 16; o > 0; o >>= 1) {
        nwl += __shfl_down_sync(0xffffffffu, nwl, o);
        wv  += __shfl_down_sync(0xffffffffu, wv,  o);
    }
    __shared__ float sh[16];
    int lane = threadIdx.x & 31;
    int wid  = threadIdx.x >> 5;
    if (lane == 0) { sh[wid] = nwl; sh[8 + wid] = wv; }
    __syncthreads();
    if (threadIdx.x == 0) {
        float an = 0.0f, ad = 0.0f;
#pragma unroll
        for (int i = 0; i < 8; i++) { an += sh[i]; ad += sh[8 + i]; }
        atomicAdd(&g_num[cam], an);
        atomicAdd(&g_den[cam], ad);
    }
}

__global__ void finalize_kernel(float* out)
{
    if (threadIdx.x == 0 && blockIdx.x == 0) {
        float L = 0.0f;
#pragma unroll
        for (int cam = 0; cam < NCAM; cam++) {
            L += g_num[cam] / fmaxf(g_den[cam], 1e-8f);
            g_num[cam] = 0.0f;   // reset accumulators for next replay
            g_den[cam] = 0.0f;
        }
        out[0] = L / (float)NCAM;
    }
}

// One-time side-stream + fork/join events. Created on the (uncaptured)
// correctness call; captured calls only record/wait — graph-legal fork-join.
static cudaStream_t get_side_stream() {
    static cudaStream_t s = [] {
        cudaStream_t t;
        cudaStreamCreateWithFlags(&t, cudaStreamNonBlocking);
        return t;
    }();
    return s;
}
static cudaEvent_t get_event(int which) {
    static cudaEvent_t e[2] = { [] {
        cudaEvent_t t;
        cudaEventCreateWithFlags(&t, cudaEventDisableTiming);
        return t;
    }(), [] {
        cudaEvent_t t;
        cudaEventCreateWithFlags(&t, cudaEventDisableTiming);
        return t;
    }() };
    return e[which];
}

extern "C" void kernel_launch(void* const* d_in, const int* in_sizes, int n_in,
                              void* d_out, int out_size)
{
    const float* voxel_feats = (const float*)d_in[0];
    const float* density     = (const float*)d_in[1];
    const float* viewmats    = (const float*)d_in[2];
    const float* Ks          = (const float*)d_in[3];
    const int*   gt_sem      = (const int*)d_in[4];
    const float* pc_xyz      = (const float*)d_in[5];
    const float* cls_w       = (const float*)d_in[6];

    cudaStream_t s1 = get_side_stream();
    cudaEvent_t eFork = get_event(0);
    cudaEvent_t eJoin = get_event(1);

    // fork: odd-camera chain runs on s1, concurrent with the even chain
    cudaEventRecord(eFork, 0);
    cudaStreamWaitEvent(s1, eFork, 0);

    for (int cam = 0; cam < NCAM; cam++) {
        int buf = cam & 1;
        cudaStream_t st = (cam & 1) ? s1 : 0;
        splat_kernel<<<(NPTS + 255) / 256, 256, 0, st>>>(cam, buf, voxel_feats, density,
                                                         viewmats, Ks, pc_xyz);
        loss_kernel<<<HW / 2048, 256, 0, st>>>(cam, buf, gt_sem, cls_w);
    }

    // join: finalize after both chains complete
    cudaEventRecord(eJoin, s1);
    cudaStreamWaitEvent(0, eJoin, 0);
    finalize_kernel<<<1, 32>>>((float*)d_out);
}